// round 1
// baseline (speedup 1.0000x reference)
#include <cuda_runtime.h>

#define BB 2
#define SS 1024
#define DD 128

// Scratch (device globals; allocation-free per harness rules)
__device__ float g_Q[BB*SS*DD];
__device__ float g_K[BB*SS*DD];
__device__ float g_V[BB*SS*DD];
__device__ float g_P[BB*SS*SS];      // unnormalized exp(10*truth)
__device__ float g_rinv[BB*SS];      // 1 / rowsum

// ---------------------------------------------------------------------------
// K1: Q/K/V projection.  Out[row,e] = act( sum_d x[row,d] * W[e,d] + b[e] )
// grid (B*S/32, 3), block 256. 32-row tile, full 128 e, d chunked by 32.
// ---------------------------------------------------------------------------
__global__ __launch_bounds__(256) void qkv_kernel(
    const float* __restrict__ x,
    const float* __restrict__ Wq, const float* __restrict__ bq,
    const float* __restrict__ Wk, const float* __restrict__ bk,
    const float* __restrict__ Wv, const float* __restrict__ bv)
{
    __shared__ float xs[32*33];
    __shared__ float ws[128*33];
    const int t  = threadIdx.x;
    const int tx = t & 15;          // -> e = tx + 16*j  (strided: conflict-free, coalesced stores)
    const int ty = t >> 4;          // -> rows ty, ty+16
    const int mat = blockIdx.y;
    const int rowbase = blockIdx.x * 32;

    const float* W    = (mat == 0) ? Wq : (mat == 1) ? Wk : Wv;
    const float* bias = (mat == 0) ? bq : (mat == 1) ? bk : bv;

    float acc[2][8];
    #pragma unroll
    for (int i = 0; i < 2; i++)
        #pragma unroll
        for (int j = 0; j < 8; j++) acc[i][j] = 0.f;

    for (int dc = 0; dc < DD; dc += 32) {
        __syncthreads();
        #pragma unroll
        for (int i = 0; i < 16; i++) {              // W chunk [128][32]
            int lin = t + i*256;
            int e = lin >> 5, dd = lin & 31;
            ws[e*33 + dd] = W[e*DD + dc + dd];
        }
        #pragma unroll
        for (int i = 0; i < 4; i++) {               // x chunk [32][32]
            int lin = t + i*256;
            int r = lin >> 5, dd = lin & 31;
            xs[r*33 + dd] = x[(rowbase + r)*DD + dc + dd];
        }
        __syncthreads();
        #pragma unroll 8
        for (int d = 0; d < 32; d++) {
            float x0 = xs[ty*33 + d];
            float x1 = xs[(ty+16)*33 + d];
            #pragma unroll
            for (int j = 0; j < 8; j++) {
                float w = ws[(tx + 16*j)*33 + d];
                acc[0][j] += x0 * w;
                acc[1][j] += x1 * w;
            }
        }
    }

    float* out = (mat == 0) ? g_Q : (mat == 1) ? g_K : g_V;
    #pragma unroll
    for (int i = 0; i < 2; i++) {
        int r = rowbase + ty + 16*i;
        #pragma unroll
        for (int j = 0; j < 8; j++) {
            int e = tx + 16*j;
            float v = acc[i][j] + bias[e];
            if (mat < 2) v = 1.f / (1.f + __expf(-v));   // sigmoid for Q,K
            out[r*DD + e] = v;
        }
    }
}

// ---------------------------------------------------------------------------
// K2: P[q,k] = exp(10 * truth), truth = 1 - (1/128) sum_d relu(Q[q,d]-K[k,d]),
// masked (causal, k>q) -> truth = 0 -> P = 1.   No max-subtraction needed:
// 10*truth in [0,10], exp bounded by e^10.
// grid (S/64, S/64, B), block 256, 4x4 microtile, 64x64 tile.
// ---------------------------------------------------------------------------
__global__ __launch_bounds__(256) void score_kernel(const int* __restrict__ maskflag)
{
    __shared__ float qs[64*65];
    __shared__ float ks[64*65];
    const int t  = threadIdx.x;
    const int tx = t & 15;          // -> k = tx + 16*j
    const int ty = t >> 4;          // -> q = ty + 16*i
    const int kt = blockIdx.x * 64;
    const int qt = blockIdx.y * 64;
    const int b  = blockIdx.z;
    const int causal = (maskflag[0] != 0);

    const float* Qb = g_Q + b*SS*DD;
    const float* Kb = g_K + b*SS*DD;

    float acc[4][4];
    #pragma unroll
    for (int i = 0; i < 4; i++)
        #pragma unroll
        for (int j = 0; j < 4; j++) acc[i][j] = 0.f;

    for (int dc = 0; dc < DD; dc += 64) {
        __syncthreads();
        #pragma unroll
        for (int i = 0; i < 16; i++) {              // [64 rows][64 d] each
            int lin = t + i*256;
            int r = lin >> 6, dd = lin & 63;
            qs[r*65 + dd] = Qb[(qt + r)*DD + dc + dd];
            ks[r*65 + dd] = Kb[(kt + r)*DD + dc + dd];
        }
        __syncthreads();
        #pragma unroll 4
        for (int d = 0; d < 64; d++) {
            float qf[4], kf[4];
            #pragma unroll
            for (int i = 0; i < 4; i++) qf[i] = qs[(ty + 16*i)*65 + d];
            #pragma unroll
            for (int j = 0; j < 4; j++) kf[j] = ks[(tx + 16*j)*65 + d];
            #pragma unroll
            for (int i = 0; i < 4; i++)
                #pragma unroll
                for (int j = 0; j < 4; j++)
                    acc[i][j] += fmaxf(qf[i] - kf[j], 0.f);
        }
    }

    float* Pb = g_P + b*SS*SS;
    #pragma unroll
    for (int i = 0; i < 4; i++) {
        int q = qt + ty + 16*i;
        #pragma unroll
        for (int j = 0; j < 4; j++) {
            int k = kt + tx + 16*j;
            float truth = 1.f - acc[i][j] * (1.f/128.f);
            if (causal && k > q) truth = 0.f;
            Pb[q*SS + k] = __expf(10.f * truth);
        }
    }
}

// ---------------------------------------------------------------------------
// K3: rinv[row] = 1 / sum_k P[row,k].  One warp per row.
// grid B*S/8, block 256.
// ---------------------------------------------------------------------------
__global__ __launch_bounds__(256) void rowsum_kernel()
{
    int row  = blockIdx.x * 8 + (threadIdx.x >> 5);   // [0, B*S)
    int lane = threadIdx.x & 31;
    const float* p = g_P + row*SS;
    float s = 0.f;
    #pragma unroll 4
    for (int i = lane; i < SS; i += 32) s += p[i];
    #pragma unroll
    for (int o = 16; o > 0; o >>= 1) s += __shfl_xor_sync(0xffffffffu, s, o);
    if (lane == 0) g_rinv[row] = 1.f / s;
}

// ---------------------------------------------------------------------------
// K4: out[q,d] = rinv[q] * sum_k P[q,k] * V[k,d]
// grid (S/16, B), block 256. 16q x 128d tile, k chunked by 64.
// ---------------------------------------------------------------------------
__global__ __launch_bounds__(256) void out_kernel(float* __restrict__ out)
{
    __shared__ float ps[16*65];
    __shared__ float vs[64*128];
    const int t  = threadIdx.x;
    const int tx = t & 31;          // d = tx*4 (float4)
    const int ty = t >> 5;          // q = ty, ty+8
    const int qt = blockIdx.x * 16;
    const int b  = blockIdx.y;

    const float* Pb = g_P + b*SS*SS;
    const float* Vb = g_V + b*SS*DD;

    float acc[2][4] = {{0.f,0.f,0.f,0.f},{0.f,0.f,0.f,0.f}};

    for (int kc = 0; kc < SS; kc += 64) {
        __syncthreads();
        #pragma unroll
        for (int i = 0; i < 4; i++) {               // P tile [16][64]
            int lin = t + i*256;
            int r = lin >> 6, c = lin & 63;
            ps[r*65 + c] = Pb[(qt + r)*SS + kc + c];
        }
        #pragma unroll
        for (int i = 0; i < 8; i++) {               // V tile [64][128]
            int lin = t + i*256;
            int r = lin >> 5, c = (lin & 31) * 4;
            *(float4*)(vs + r*128 + c) = *(const float4*)(Vb + (kc + r)*DD + c);
        }
        __syncthreads();
        #pragma unroll 4
        for (int k = 0; k < 64; k++) {
            float p0 = ps[ty*65 + k];
            float p1 = ps[(ty+8)*65 + k];
            float4 v = *(const float4*)(vs + k*128 + tx*4);
            acc[0][0] += p0*v.x; acc[0][1] += p0*v.y; acc[0][2] += p0*v.z; acc[0][3] += p0*v.w;
            acc[1][0] += p1*v.x; acc[1][1] += p1*v.y; acc[1][2] += p1*v.z; acc[1][3] += p1*v.w;
        }
    }

    #pragma unroll
    for (int i = 0; i < 2; i++) {
        int q = qt + ty + 8*i;
        float rv = g_rinv[b*SS + q];
        float4 o;
        o.x = acc[i][0]*rv; o.y = acc[i][1]*rv; o.z = acc[i][2]*rv; o.w = acc[i][3]*rv;
        *(float4*)(out + (b*SS + q)*DD + tx*4) = o;
    }
}

// ---------------------------------------------------------------------------
extern "C" void kernel_launch(void* const* d_in, const int* in_sizes, int n_in,
                              void* d_out, int out_size)
{
    const float* x  = (const float*)d_in[0];
    const float* Wq = (const float*)d_in[1];
    const float* bq = (const float*)d_in[2];
    const float* Wk = (const float*)d_in[3];
    const float* bk = (const float*)d_in[4];
    const float* Wv = (const float*)d_in[5];
    const float* bv = (const float*)d_in[6];
    const int*  msk = (const int*)d_in[7];
    float* out = (float*)d_out;

    qkv_kernel  <<<dim3(BB*SS/32, 3), 256>>>(x, Wq, bq, Wk, bk, Wv, bv);
    score_kernel<<<dim3(SS/64, SS/64, BB), 256>>>(msk);
    rowsum_kernel<<<BB*SS/8, 256>>>();
    out_kernel  <<<dim3(SS/16, BB), 256>>>(out);
}

// round 2
// speedup vs baseline: 1.2866x; 1.2866x over previous
#include <cuda_runtime.h>

#define BB 2
#define SS 1024
#define DD 128
#define KSPLIT 8

// Scratch (device globals; allocation-free per harness rules)
__device__ float g_Q[BB*SS*DD];
__device__ float g_K[BB*SS*DD];
__device__ float g_V[BB*SS*DD];
__device__ float g_P[BB*SS*SS];              // unnormalized exp(10*truth)
__device__ float g_rinv[BB*SS];              // 1 / rowsum
__device__ float g_part[KSPLIT][BB*SS*DD];   // split-K partials for P@V

// ---------------------------------------------------------------------------
// K1: Q/K/V projection.  Out[row,e] = act( sum_d x[row,d] * W[e,d] + b[e] )
// grid (B*S/32, 3), block 256.
// ---------------------------------------------------------------------------
__global__ __launch_bounds__(256) void qkv_kernel(
    const float* __restrict__ x,
    const float* __restrict__ Wq, const float* __restrict__ bq,
    const float* __restrict__ Wk, const float* __restrict__ bk,
    const float* __restrict__ Wv, const float* __restrict__ bv)
{
    __shared__ float xs[32*33];
    __shared__ float ws[128*33];
    const int t  = threadIdx.x;
    const int tx = t & 15;
    const int ty = t >> 4;
    const int mat = blockIdx.y;
    const int rowbase = blockIdx.x * 32;

    const float* W    = (mat == 0) ? Wq : (mat == 1) ? Wk : Wv;
    const float* bias = (mat == 0) ? bq : (mat == 1) ? bk : bv;

    float acc[2][8];
    #pragma unroll
    for (int i = 0; i < 2; i++)
        #pragma unroll
        for (int j = 0; j < 8; j++) acc[i][j] = 0.f;

    for (int dc = 0; dc < DD; dc += 32) {
        __syncthreads();
        #pragma unroll
        for (int i = 0; i < 16; i++) {
            int lin = t + i*256;
            int e = lin >> 5, dd = lin & 31;
            ws[e*33 + dd] = W[e*DD + dc + dd];
        }
        #pragma unroll
        for (int i = 0; i < 4; i++) {
            int lin = t + i*256;
            int r = lin >> 5, dd = lin & 31;
            xs[r*33 + dd] = x[(rowbase + r)*DD + dc + dd];
        }
        __syncthreads();
        #pragma unroll 8
        for (int d = 0; d < 32; d++) {
            float x0 = xs[ty*33 + d];
            float x1 = xs[(ty+16)*33 + d];
            #pragma unroll
            for (int j = 0; j < 8; j++) {
                float w = ws[(tx + 16*j)*33 + d];
                acc[0][j] += x0 * w;
                acc[1][j] += x1 * w;
            }
        }
    }

    float* out = (mat == 0) ? g_Q : (mat == 1) ? g_K : g_V;
    #pragma unroll
    for (int i = 0; i < 2; i++) {
        int r = rowbase + ty + 16*i;
        #pragma unroll
        for (int j = 0; j < 8; j++) {
            int e = tx + 16*j;
            float v = acc[i][j] + bias[e];
            if (mat < 2) v = 1.f / (1.f + __expf(-v));
            out[r*DD + e] = v;
        }
    }
}

// ---------------------------------------------------------------------------
// K2: P[q,k] = exp(10 * truth), truth = 1 - (1/128) sum_d relu(Q[q,d]-K[k,d]),
// masked (causal, k>q) -> truth = 0 -> P = 1.
// grid (S/64, S/64, B), block 256, 4x4 microtile.
// ---------------------------------------------------------------------------
__global__ __launch_bounds__(256) void score_kernel(const int* __restrict__ maskflag)
{
    __shared__ float qs[64*65];
    __shared__ float ks[64*65];
    const int t  = threadIdx.x;
    const int tx = t & 15;
    const int ty = t >> 4;
    const int kt = blockIdx.x * 64;
    const int qt = blockIdx.y * 64;
    const int b  = blockIdx.z;
    const int causal = (maskflag[0] != 0);

    const float* Qb = g_Q + b*SS*DD;
    const float* Kb = g_K + b*SS*DD;

    float acc[4][4];
    #pragma unroll
    for (int i = 0; i < 4; i++)
        #pragma unroll
        for (int j = 0; j < 4; j++) acc[i][j] = 0.f;

    for (int dc = 0; dc < DD; dc += 64) {
        __syncthreads();
        #pragma unroll
        for (int i = 0; i < 16; i++) {
            int lin = t + i*256;
            int r = lin >> 6, dd = lin & 63;
            qs[r*65 + dd] = Qb[(qt + r)*DD + dc + dd];
            ks[r*65 + dd] = Kb[(kt + r)*DD + dc + dd];
        }
        __syncthreads();
        #pragma unroll 4
        for (int d = 0; d < 64; d++) {
            float qf[4], kf[4];
            #pragma unroll
            for (int i = 0; i < 4; i++) qf[i] = qs[(ty + 16*i)*65 + d];
            #pragma unroll
            for (int j = 0; j < 4; j++) kf[j] = ks[(tx + 16*j)*65 + d];
            #pragma unroll
            for (int i = 0; i < 4; i++)
                #pragma unroll
                for (int j = 0; j < 4; j++)
                    acc[i][j] += fmaxf(qf[i] - kf[j], 0.f);
        }
    }

    float* Pb = g_P + b*SS*SS;
    #pragma unroll
    for (int i = 0; i < 4; i++) {
        int q = qt + ty + 16*i;
        #pragma unroll
        for (int j = 0; j < 4; j++) {
            int k = kt + tx + 16*j;
            float truth = 1.f - acc[i][j] * (1.f/128.f);
            if (causal && k > q) truth = 0.f;
            Pb[q*SS + k] = __expf(10.f * truth);
        }
    }
}

// ---------------------------------------------------------------------------
// K3: rinv[row] = 1 / sum_k P[row,k].  One warp per row.
// ---------------------------------------------------------------------------
__global__ __launch_bounds__(256) void rowsum_kernel()
{
    int row  = blockIdx.x * 8 + (threadIdx.x >> 5);
    int lane = threadIdx.x & 31;
    const float* p = g_P + row*SS;
    float s = 0.f;
    #pragma unroll 8
    for (int i = lane; i < SS; i += 32) s += p[i];
    #pragma unroll
    for (int o = 16; o > 0; o >>= 1) s += __shfl_xor_sync(0xffffffffu, s, o);
    if (lane == 0) g_rinv[row] = 1.f / s;
}

// ---------------------------------------------------------------------------
// K4a: split-K partial of P@V.
// grid (S/32, B, KSPLIT), block 256.  Tile: 32q x 128d, k-range SS/KSPLIT=128.
// Microtile 4q x 4d per thread: per k -> 4 broadcast LDS + 1 LDS.128 + 16 FFMA.
// ---------------------------------------------------------------------------
__global__ __launch_bounds__(256) void out_part_kernel()
{
    __shared__ float ps[32*65];
    __shared__ float vs[64*128];
    const int t  = threadIdx.x;
    const int tx = t & 31;          // d = tx*4 (float4)
    const int ty = t >> 5;          // q = ty + 8*i, i<4
    const int qt = blockIdx.x * 32;
    const int b  = blockIdx.y;
    const int k0 = blockIdx.z * (SS/KSPLIT);

    const float* Pb = g_P + b*SS*SS;
    const float* Vb = g_V + b*SS*DD;

    float acc[4][4];
    #pragma unroll
    for (int i = 0; i < 4; i++)
        #pragma unroll
        for (int j = 0; j < 4; j++) acc[i][j] = 0.f;

    for (int kc = 0; kc < SS/KSPLIT; kc += 64) {
        __syncthreads();
        #pragma unroll
        for (int i = 0; i < 8; i++) {               // P tile [32][64]
            int lin = t + i*256;
            int r = lin >> 6, c = lin & 63;
            ps[r*65 + c] = Pb[(qt + r)*SS + k0 + kc + c];
        }
        #pragma unroll
        for (int i = 0; i < 8; i++) {               // V tile [64][128]
            int lin = t + i*256;
            int r = lin >> 5, c = (lin & 31) * 4;
            *(float4*)(vs + r*128 + c) = *(const float4*)(Vb + (k0 + kc + r)*DD + c);
        }
        __syncthreads();
        #pragma unroll 8
        for (int k = 0; k < 64; k++) {
            float pf[4];
            #pragma unroll
            for (int i = 0; i < 4; i++) pf[i] = ps[(ty + 8*i)*65 + k];
            float4 v = *(const float4*)(vs + k*128 + tx*4);
            #pragma unroll
            for (int i = 0; i < 4; i++) {
                acc[i][0] += pf[i]*v.x; acc[i][1] += pf[i]*v.y;
                acc[i][2] += pf[i]*v.z; acc[i][3] += pf[i]*v.w;
            }
        }
    }

    float* dst = g_part[blockIdx.z];
    #pragma unroll
    for (int i = 0; i < 4; i++) {
        int q = qt + ty + 8*i;
        float4 o;
        o.x = acc[i][0]; o.y = acc[i][1]; o.z = acc[i][2]; o.w = acc[i][3];
        *(float4*)(dst + (b*SS + q)*DD + tx*4) = o;
    }
}

// ---------------------------------------------------------------------------
// K4b: deterministic reduce over KSPLIT partials, scale by rinv.
// grid (B*S*D / (256*4)), block 256; one float4 per thread.
// ---------------------------------------------------------------------------
__global__ __launch_bounds__(256) void out_reduce_kernel(float* __restrict__ out)
{
    int idx4 = blockIdx.x * 256 + threadIdx.x;       // float4 index
    int base = idx4 * 4;
    float4 s = *(const float4*)(&g_part[0][base]);
    #pragma unroll
    for (int j = 1; j < KSPLIT; j++) {
        float4 p = *(const float4*)(&g_part[j][base]);
        s.x += p.x; s.y += p.y; s.z += p.z; s.w += p.w;
    }
    int row = base / DD;                              // = b*SS + q
    float rv = g_rinv[row];
    s.x *= rv; s.y *= rv; s.z *= rv; s.w *= rv;
    *(float4*)(out + base) = s;
}

// ---------------------------------------------------------------------------
extern "C" void kernel_launch(void* const* d_in, const int* in_sizes, int n_in,
                              void* d_out, int out_size)
{
    const float* x  = (const float*)d_in[0];
    const float* Wq = (const float*)d_in[1];
    const float* bq = (const float*)d_in[2];
    const float* Wk = (const float*)d_in[3];
    const float* bk = (const float*)d_in[4];
    const float* Wv = (const float*)d_in[5];
    const float* bv = (const float*)d_in[6];
    const int*  msk = (const int*)d_in[7];
    float* out = (float*)d_out;

    qkv_kernel    <<<dim3(BB*SS/32, 3), 256>>>(x, Wq, bq, Wk, bk, Wv, bv);
    score_kernel  <<<dim3(SS/64, SS/64, BB), 256>>>(msk);
    rowsum_kernel <<<BB*SS/8, 256>>>();
    out_part_kernel  <<<dim3(SS/32, BB, KSPLIT), 256>>>();
    out_reduce_kernel<<<BB*SS*DD/1024, 256>>>(out);
}

// round 3
// speedup vs baseline: 1.3104x; 1.0185x over previous
#include <cuda_runtime.h>

#define BB 2
#define SS 1024
#define DD 128
#define NCHUNK 16          // P@V split-K chunks of 64 k each

// Scratch (device globals; allocation-free per harness rules)
__device__ float g_Q[BB*SS*DD];
__device__ float g_K[BB*SS*DD];
__device__ float g_V[BB*SS*DD];
__device__ float g_P[BB*SS*SS];               // exp(10*truth), lower triangle only when causal
__device__ float g_rinv[BB*SS];               // 1 / (rowsum + masked count)
__device__ float g_part[NCHUNK][BB*SS*DD];    // split-K partials for P@V
__device__ float g_vseg[BB*16*DD];            // per-64-row segment sums of V
__device__ float g_vpre[BB*SS*DD];            // inclusive prefix sums of V

// ---------------------------------------------------------------------------
// K1: Q/K/V projection.  Out[row,e] = act( sum_d x[row,d] * W[e,d] + b[e] )
// ---------------------------------------------------------------------------
__global__ __launch_bounds__(256) void qkv_kernel(
    const float* __restrict__ x,
    const float* __restrict__ Wq, const float* __restrict__ bq,
    const float* __restrict__ Wk, const float* __restrict__ bk,
    const float* __restrict__ Wv, const float* __restrict__ bv)
{
    __shared__ float xs[32*33];
    __shared__ float ws[128*33];
    const int t  = threadIdx.x;
    const int tx = t & 15;
    const int ty = t >> 4;
    const int mat = blockIdx.y;
    const int rowbase = blockIdx.x * 32;

    const float* W    = (mat == 0) ? Wq : (mat == 1) ? Wk : Wv;
    const float* bias = (mat == 0) ? bq : (mat == 1) ? bk : bv;

    float acc[2][8];
    #pragma unroll
    for (int i = 0; i < 2; i++)
        #pragma unroll
        for (int j = 0; j < 8; j++) acc[i][j] = 0.f;

    for (int dc = 0; dc < DD; dc += 32) {
        __syncthreads();
        #pragma unroll
        for (int i = 0; i < 16; i++) {
            int lin = t + i*256;
            int e = lin >> 5, dd = lin & 31;
            ws[e*33 + dd] = W[e*DD + dc + dd];
        }
        #pragma unroll
        for (int i = 0; i < 4; i++) {
            int lin = t + i*256;
            int r = lin >> 5, dd = lin & 31;
            xs[r*33 + dd] = x[(rowbase + r)*DD + dc + dd];
        }
        __syncthreads();
        #pragma unroll 8
        for (int d = 0; d < 32; d++) {
            float x0 = xs[ty*33 + d];
            float x1 = xs[(ty+16)*33 + d];
            #pragma unroll
            for (int j = 0; j < 8; j++) {
                float w = ws[(tx + 16*j)*33 + d];
                acc[0][j] += x0 * w;
                acc[1][j] += x1 * w;
            }
        }
    }

    float* out = (mat == 0) ? g_Q : (mat == 1) ? g_K : g_V;
    #pragma unroll
    for (int i = 0; i < 2; i++) {
        int r = rowbase + ty + 16*i;
        #pragma unroll
        for (int j = 0; j < 8; j++) {
            int e = tx + 16*j;
            float v = acc[i][j] + bias[e];
            if (mat < 2) v = 1.f / (1.f + __expf(-v));
            out[r*DD + e] = v;
        }
    }
}

// ---------------------------------------------------------------------------
// V prefix sums (for analytic masked-region contribution).
// vseg: per-64-row segment sums.  vpre: inclusive per-row prefix.
// ---------------------------------------------------------------------------
__global__ __launch_bounds__(128) void vseg_kernel()
{
    int b = blockIdx.x, s = blockIdx.y, d = threadIdx.x;
    const float* Vb = g_V + b*SS*DD;
    float a = 0.f;
    #pragma unroll 8
    for (int r = 0; r < 64; r++) a += Vb[(s*64 + r)*DD + d];
    g_vseg[(b*16 + s)*DD + d] = a;
}

__global__ __launch_bounds__(128) void vpre_kernel()
{
    int b = blockIdx.x, s = blockIdx.y, d = threadIdx.x;
    const float* Vb = g_V + b*SS*DD;
    float a = 0.f;
    for (int sp = 0; sp < s; sp++) a += g_vseg[(b*16 + sp)*DD + d];
    #pragma unroll 4
    for (int r = 0; r < 64; r++) {
        a += Vb[(s*64 + r)*DD + d];
        g_vpre[(b*SS + s*64 + r)*DD + d] = a;
    }
}

// ---------------------------------------------------------------------------
// K2: P[q,k] = exp(10*truth), truth = 1 - (1/128) sum_d relu(Q[q,d]-K[k,d]).
// Causal: tiles kt>qt skipped entirely; diagonal tile stores 0 for k>q
// (masked entries handled analytically downstream).
// ---------------------------------------------------------------------------
__global__ __launch_bounds__(256) void score_kernel(const int* __restrict__ maskflag)
{
    const int kt = blockIdx.x * 64;
    const int qt = blockIdx.y * 64;
    const int causal = (maskflag[0] != 0);
    if (causal && kt > qt) return;

    __shared__ float qs[64*65];
    __shared__ float ks[64*65];
    const int t  = threadIdx.x;
    const int tx = t & 15;
    const int ty = t >> 4;
    const int b  = blockIdx.z;

    const float* Qb = g_Q + b*SS*DD;
    const float* Kb = g_K + b*SS*DD;

    float acc[4][4];
    #pragma unroll
    for (int i = 0; i < 4; i++)
        #pragma unroll
        for (int j = 0; j < 4; j++) acc[i][j] = 0.f;

    for (int dc = 0; dc < DD; dc += 64) {
        __syncthreads();
        #pragma unroll
        for (int i = 0; i < 16; i++) {
            int lin = t + i*256;
            int r = lin >> 6, dd = lin & 63;
            qs[r*65 + dd] = Qb[(qt + r)*DD + dc + dd];
            ks[r*65 + dd] = Kb[(kt + r)*DD + dc + dd];
        }
        __syncthreads();
        #pragma unroll 4
        for (int d = 0; d < 64; d++) {
            float qf[4], kf[4];
            #pragma unroll
            for (int i = 0; i < 4; i++) qf[i] = qs[(ty + 16*i)*65 + d];
            #pragma unroll
            for (int j = 0; j < 4; j++) kf[j] = ks[(tx + 16*j)*65 + d];
            #pragma unroll
            for (int i = 0; i < 4; i++)
                #pragma unroll
                for (int j = 0; j < 4; j++)
                    acc[i][j] += fmaxf(qf[i] - kf[j], 0.f);
        }
    }

    float* Pb = g_P + b*SS*SS;
    #pragma unroll
    for (int i = 0; i < 4; i++) {
        int q = qt + ty + 16*i;
        #pragma unroll
        for (int j = 0; j < 4; j++) {
            int k = kt + tx + 16*j;
            float val = __expf(10.f * (1.f - acc[i][j] * (1.f/128.f)));
            if (causal && k > q) val = 0.f;   // analytic term covers masked entries
            Pb[q*SS + k] = val;
        }
    }
}

// ---------------------------------------------------------------------------
// K3: rinv[row] = 1 / (sum_{k<=q} P + masked_count).  One warp per row.
// ---------------------------------------------------------------------------
__global__ __launch_bounds__(256) void rowsum_kernel(const int* __restrict__ maskflag)
{
    const int causal = (maskflag[0] != 0);
    int row  = blockIdx.x * 8 + (threadIdx.x >> 5);
    int lane = threadIdx.x & 31;
    int q = row & (SS-1);
    int kend = causal ? (((q >> 6) + 1) << 6) : SS;
    const float* p = g_P + row*SS;
    float s = 0.f;
    #pragma unroll 4
    for (int i = lane; i < kend; i += 32) s += p[i];
    #pragma unroll
    for (int o = 16; o > 0; o >>= 1) s += __shfl_xor_sync(0xffffffffu, s, o);
    if (lane == 0) {
        float extra = causal ? (float)(SS - 1 - q) : 0.f;   // exp(0)=1 each
        g_rinv[row] = 1.f / (s + extra);
    }
}

// ---------------------------------------------------------------------------
// K4a: split-K partial of P@V over one 64-k chunk.
// grid (S/32, B, NCHUNK), block 128.  Microtile 4q x 8d per thread.
// Causal: chunk skipped if entirely above diagonal for this q-tile.
// ---------------------------------------------------------------------------
__global__ __launch_bounds__(128) void pv_part_kernel(const int* __restrict__ maskflag)
{
    const int qt = blockIdx.x * 32;
    const int k0 = blockIdx.z * 64;
    const int causal = (maskflag[0] != 0);
    if (causal && k0 > qt + 31) return;

    __shared__ float ps[32*65];
    __shared__ float vs[64*128];
    const int t  = threadIdx.x;
    const int tx = t & 15;          // d pair: tx*4 and tx*4+64
    const int ty = t >> 4;          // q = ty + 8*i
    const int b  = blockIdx.y;

    const float* Pb = g_P + b*SS*SS;
    const float* Vb = g_V + b*SS*DD;

    #pragma unroll
    for (int i = 0; i < 16; i++) {               // P tile [32][64]
        int lin = t + i*128;
        int r = lin >> 6, c = lin & 63;
        ps[r*65 + c] = Pb[(qt + r)*SS + k0 + c];
    }
    #pragma unroll
    for (int i = 0; i < 16; i++) {               // V tile [64][128]
        int lin = t + i*128;
        int r = lin >> 5, c = (lin & 31) * 4;
        *(float4*)(vs + r*128 + c) = *(const float4*)(Vb + (k0 + r)*DD + c);
    }
    __syncthreads();

    float4 acc[4][2];
    #pragma unroll
    for (int i = 0; i < 4; i++)
        #pragma unroll
        for (int j = 0; j < 2; j++) acc[i][j] = make_float4(0.f,0.f,0.f,0.f);

    #pragma unroll 4
    for (int k = 0; k < 64; k++) {
        float pf[4];
        #pragma unroll
        for (int i = 0; i < 4; i++) pf[i] = ps[(ty + 8*i)*65 + k];
        float4 v0 = *(const float4*)(vs + k*128 + tx*4);
        float4 v1 = *(const float4*)(vs + k*128 + 64 + tx*4);
        #pragma unroll
        for (int i = 0; i < 4; i++) {
            acc[i][0].x += pf[i]*v0.x; acc[i][0].y += pf[i]*v0.y;
            acc[i][0].z += pf[i]*v0.z; acc[i][0].w += pf[i]*v0.w;
            acc[i][1].x += pf[i]*v1.x; acc[i][1].y += pf[i]*v1.y;
            acc[i][1].z += pf[i]*v1.z; acc[i][1].w += pf[i]*v1.w;
        }
    }

    float* dst = g_part[blockIdx.z];
    #pragma unroll
    for (int i = 0; i < 4; i++) {
        int q = qt + ty + 8*i;
        *(float4*)(dst + (b*SS + q)*DD + tx*4)      = acc[i][0];
        *(float4*)(dst + (b*SS + q)*DD + 64 + tx*4) = acc[i][1];
    }
}

// ---------------------------------------------------------------------------
// K4b: deterministic reduce over active chunks + analytic masked term, * rinv.
// ---------------------------------------------------------------------------
__global__ __launch_bounds__(256) void out_reduce_kernel(float* __restrict__ out,
                                                          const int* __restrict__ maskflag)
{
    const int causal = (maskflag[0] != 0);
    int idx4 = blockIdx.x * 256 + threadIdx.x;
    int base = idx4 * 4;
    int row  = base >> 7;              // b*SS + q
    int q    = row & (SS-1);
    int b    = row >> 10;

    int nc = causal ? ((((q & ~31) + 31) >> 6) + 1) : NCHUNK;

    float4 s = make_float4(0.f,0.f,0.f,0.f);
    for (int j = 0; j < nc; j++) {
        float4 p = *(const float4*)(&g_part[j][base]);
        s.x += p.x; s.y += p.y; s.z += p.z; s.w += p.w;
    }
    if (causal) {
        // masked region: sum_{k>q} 1 * V[k] = Vtot - Vpre[q]
        int doff = base & 127;
        const float* vtot = g_vpre + ((b << 10) + SS - 1)*DD + doff;
        const float* vpre = g_vpre + row*DD + doff;
        float4 vt = *(const float4*)vtot;
        float4 vp = *(const float4*)vpre;
        s.x += vt.x - vp.x; s.y += vt.y - vp.y;
        s.z += vt.z - vp.z; s.w += vt.w - vp.w;
    }
    float rv = g_rinv[row];
    s.x *= rv; s.y *= rv; s.z *= rv; s.w *= rv;
    *(float4*)(out + base) = s;
}

// ---------------------------------------------------------------------------
extern "C" void kernel_launch(void* const* d_in, const int* in_sizes, int n_in,
                              void* d_out, int out_size)
{
    const float* x  = (const float*)d_in[0];
    const float* Wq = (const float*)d_in[1];
    const float* bq = (const float*)d_in[2];
    const float* Wk = (const float*)d_in[3];
    const float* bk = (const float*)d_in[4];
    const float* Wv = (const float*)d_in[5];
    const float* bv = (const float*)d_in[6];
    const int*  msk = (const int*)d_in[7];
    float* out = (float*)d_out;

    qkv_kernel    <<<dim3(BB*SS/32, 3), 256>>>(x, Wq, bq, Wk, bk, Wv, bv);
    vseg_kernel   <<<dim3(BB, 16), 128>>>();
    vpre_kernel   <<<dim3(BB, 16), 128>>>();
    score_kernel  <<<dim3(SS/64, SS/64, BB), 256>>>(msk);
    rowsum_kernel <<<BB*SS/8, 256>>>(msk);
    pv_part_kernel<<<dim3(SS/32, BB, NCHUNK), 128>>>(msk);
    out_reduce_kernel<<<BB*SS*DD/1024, 256>>>(out, msk);
}

// round 4
// speedup vs baseline: 1.4475x; 1.1046x over previous
#include <cuda_runtime.h>

#define BB 2
#define SS 1024
#define DD 128
#define NCHUNK 8           // k chunks of 128

// Scratch (device globals; allocation-free per harness rules)
__device__ float g_Q[BB*SS*DD];
__device__ float g_K[BB*SS*DD];
__device__ float g_V[BB*SS*DD];
__device__ float g_sQ[BB*SS];                 // row sums of Q
__device__ float g_sK[BB*SS];                 // row sums of K
__device__ float g_part[NCHUNK][BB*SS*DD];    // split-K partial outputs
__device__ float g_rsum[NCHUNK][BB*SS];       // split-K partial row sums of exp
__device__ float g_vseg[BB*16*DD];            // per-64-row segment sums of V
__device__ float g_vpre[BB*SS*DD];            // inclusive prefix sums of V

// ---------------------------------------------------------------------------
// K1: Q/K/V projection + row-sum epilogue for Q,K.
// ---------------------------------------------------------------------------
__global__ __launch_bounds__(256) void qkv_kernel(
    const float* __restrict__ x,
    const float* __restrict__ Wq, const float* __restrict__ bq,
    const float* __restrict__ Wk, const float* __restrict__ bk,
    const float* __restrict__ Wv, const float* __restrict__ bv)
{
    __shared__ float xs[32*33];
    __shared__ float ws[128*33];
    const int t  = threadIdx.x;
    const int tx = t & 15;
    const int ty = t >> 4;
    const int mat = blockIdx.y;
    const int rowbase = blockIdx.x * 32;

    const float* W    = (mat == 0) ? Wq : (mat == 1) ? Wk : Wv;
    const float* bias = (mat == 0) ? bq : (mat == 1) ? bk : bv;

    float acc[2][8];
    #pragma unroll
    for (int i = 0; i < 2; i++)
        #pragma unroll
        for (int j = 0; j < 8; j++) acc[i][j] = 0.f;

    for (int dc = 0; dc < DD; dc += 32) {
        __syncthreads();
        #pragma unroll
        for (int i = 0; i < 16; i++) {
            int lin = t + i*256;
            int e = lin >> 5, dd = lin & 31;
            ws[e*33 + dd] = W[e*DD + dc + dd];
        }
        #pragma unroll
        for (int i = 0; i < 4; i++) {
            int lin = t + i*256;
            int r = lin >> 5, dd = lin & 31;
            xs[r*33 + dd] = x[(rowbase + r)*DD + dc + dd];
        }
        __syncthreads();
        #pragma unroll 8
        for (int d = 0; d < 32; d++) {
            float x0 = xs[ty*33 + d];
            float x1 = xs[(ty+16)*33 + d];
            #pragma unroll
            for (int j = 0; j < 8; j++) {
                float w = ws[(tx + 16*j)*33 + d];
                acc[0][j] += x0 * w;
                acc[1][j] += x1 * w;
            }
        }
    }

    float* out = (mat == 0) ? g_Q : (mat == 1) ? g_K : g_V;
    float rsum[2] = {0.f, 0.f};
    #pragma unroll
    for (int i = 0; i < 2; i++) {
        int r = rowbase + ty + 16*i;
        #pragma unroll
        for (int j = 0; j < 8; j++) {
            int e = tx + 16*j;
            float v = acc[i][j] + bias[e];
            if (mat < 2) v = 1.f / (1.f + __expf(-v));
            rsum[i] += v;
            out[r*DD + e] = v;
        }
    }
    if (mat < 2) {
        // reduce over the 16-lane tx group (rows held by same ty)
        #pragma unroll
        for (int o = 1; o < 16; o <<= 1) {
            rsum[0] += __shfl_xor_sync(0xffffffffu, rsum[0], o);
            rsum[1] += __shfl_xor_sync(0xffffffffu, rsum[1], o);
        }
        if (tx == 0) {
            float* dst = (mat == 0) ? g_sQ : g_sK;
            dst[rowbase + ty]      = rsum[0];
            dst[rowbase + ty + 16] = rsum[1];
        }
    }
}

// ---------------------------------------------------------------------------
// V prefix sums (for analytic masked-region contribution).
// ---------------------------------------------------------------------------
__global__ __launch_bounds__(128) void vseg_kernel()
{
    int b = blockIdx.x, s = blockIdx.y, d = threadIdx.x;
    const float* Vb = g_V + b*SS*DD;
    float a = 0.f;
    #pragma unroll 8
    for (int r = 0; r < 64; r++) a += Vb[(s*64 + r)*DD + d];
    g_vseg[(b*16 + s)*DD + d] = a;
}

__global__ __launch_bounds__(128) void vpre_kernel()
{
    int b = blockIdx.x, s = blockIdx.y, d = threadIdx.x;
    const float* Vb = g_V + b*SS*DD;
    float a = 0.f;
    for (int sp = 0; sp < s; sp++) a += g_vseg[(b*16 + sp)*DD + d];
    #pragma unroll 4
    for (int r = 0; r < 64; r++) {
        a += Vb[(s*64 + r)*DD + d];
        g_vpre[(b*SS + s*64 + r)*DD + d] = a;
    }
}

// ---------------------------------------------------------------------------
// Fused flash-style kernel: one block = 32-q tile x 128-k chunk.
// score (via |q-k| identity) -> exp -> rowsum (shfl) -> S@V accumulate.
// Writes chunk-partial out and rowsum; masked (k>q) entries contribute 0
// here and are handled analytically in the reduce (exp(0)=1 each).
// grid (S/32, B, NCHUNK), block 256.
// ---------------------------------------------------------------------------
__global__ __launch_bounds__(256) void fused_kernel(const int* __restrict__ maskflag)
{
    const int qt = blockIdx.x * 32;
    const int kc = blockIdx.z;
    const int causal = (maskflag[0] != 0);
    if (causal && kc*128 > qt + 31) return;

    __shared__ float qs[32*132];   // Q tile, pad 132 (float4-aligned, conflict-free)
    __shared__ float ks[32*132];   // K subtile
    __shared__ float ss[32*36];    // exp'd score subtile

    const int t  = threadIdx.x;
    const int tx = t & 15;         // score: k = k0 + tx, +16
    const int ty = t >> 4;         // score: q = qt + ty, +16
    const int tx2 = t & 31;        // pv: d = tx2*4
    const int ty2 = t >> 5;        // pv: q = ty2 + 8i
    const int b  = blockIdx.y;

    const float* Qb = g_Q + b*SS*DD;
    const float* Kb = g_K + b*SS*DD;
    const float* Vb = g_V + b*SS*DD;

    // load Q tile [32][128]
    #pragma unroll
    for (int i = 0; i < 4; i++) {
        int lin = t + i*256;
        int r = lin >> 5, c = (lin & 31) * 4;
        *(float4*)(qs + r*132 + c) = *(const float4*)(Qb + (qt + r)*DD + c);
    }
    const float sQ0 = g_sQ[b*SS + qt + ty];
    const float sQ1 = g_sQ[b*SS + qt + ty + 16];

    float4 oacc[4];
    #pragma unroll
    for (int i = 0; i < 4; i++) oacc[i] = make_float4(0.f,0.f,0.f,0.f);
    float rs0 = 0.f, rs1 = 0.f;

    for (int s = 0; s < 4; s++) {
        const int k0 = kc*128 + s*32;
        if (causal && k0 > qt + 31) break;

        __syncthreads();                       // protect ks/ss from prev iter
        #pragma unroll
        for (int i = 0; i < 4; i++) {          // load K subtile [32][128]
            int lin = t + i*256;
            int r = lin >> 5, c = (lin & 31) * 4;
            *(float4*)(ks + r*132 + c) = *(const float4*)(Kb + (k0 + r)*DD + c);
        }
        __syncthreads();

        // --- score: A = sum_d |q - k|  (2 FADD per element) ---
        float a00 = 0.f, a01 = 0.f, a10 = 0.f, a11 = 0.f;
        #pragma unroll 8
        for (int dq = 0; dq < 32; dq++) {
            float4 q0 = *(const float4*)(qs + ty*132 + dq*4);
            float4 q1 = *(const float4*)(qs + (ty+16)*132 + dq*4);
            float4 k0v = *(const float4*)(ks + tx*132 + dq*4);
            float4 k1v = *(const float4*)(ks + (tx+16)*132 + dq*4);
            a00 += fabsf(q0.x-k0v.x); a00 += fabsf(q0.y-k0v.y);
            a00 += fabsf(q0.z-k0v.z); a00 += fabsf(q0.w-k0v.w);
            a01 += fabsf(q0.x-k1v.x); a01 += fabsf(q0.y-k1v.y);
            a01 += fabsf(q0.z-k1v.z); a01 += fabsf(q0.w-k1v.w);
            a10 += fabsf(q1.x-k0v.x); a10 += fabsf(q1.y-k0v.y);
            a10 += fabsf(q1.z-k0v.z); a10 += fabsf(q1.w-k0v.w);
            a11 += fabsf(q1.x-k1v.x); a11 += fabsf(q1.y-k1v.y);
            a11 += fabsf(q1.z-k1v.z); a11 += fabsf(q1.w-k1v.w);
        }
        const float sK0 = g_sK[b*SS + k0 + tx];
        const float sK1 = g_sK[b*SS + k0 + tx + 16];

        // truth = 1 - (sQ - sK + A)/256 ; val = exp(10*truth) ; mask k>q -> 0
        float v00 = __expf(10.f - (sQ0 - sK0 + a00)*(10.f/256.f));
        float v01 = __expf(10.f - (sQ0 - sK1 + a01)*(10.f/256.f));
        float v10 = __expf(10.f - (sQ1 - sK0 + a10)*(10.f/256.f));
        float v11 = __expf(10.f - (sQ1 - sK1 + a11)*(10.f/256.f));
        if (causal) {
            int q0g = qt + ty, q1g = qt + ty + 16;
            int k0g = k0 + tx, k1g = k0 + tx + 16;
            if (k0g > q0g) v00 = 0.f;
            if (k1g > q0g) v01 = 0.f;
            if (k0g > q1g) v10 = 0.f;
            if (k1g > q1g) v11 = 0.f;
        }
        ss[ty*36 + tx]           = v00;
        ss[ty*36 + tx + 16]      = v01;
        ss[(ty+16)*36 + tx]      = v10;
        ss[(ty+16)*36 + tx + 16] = v11;

        // row sums across the 16-lane tx group
        float l0 = v00 + v01, l1 = v10 + v11;
        #pragma unroll
        for (int o = 1; o < 16; o <<= 1) {
            l0 += __shfl_xor_sync(0xffffffffu, l0, o);
            l1 += __shfl_xor_sync(0xffffffffu, l1, o);
        }
        if (tx == 0) { rs0 += l0; rs1 += l1; }
        __syncthreads();

        // --- PV: out[q][d] += sum_k S[q][k] * V[k][d]; V straight from L2 ---
        #pragma unroll 2
        for (int kq = 0; kq < 8; kq++) {
            float4 p0 = *(const float4*)(ss + (ty2    )*36 + kq*4);
            float4 p1 = *(const float4*)(ss + (ty2+ 8)*36 + kq*4);
            float4 p2 = *(const float4*)(ss + (ty2+16)*36 + kq*4);
            float4 p3 = *(const float4*)(ss + (ty2+24)*36 + kq*4);
            #pragma unroll
            for (int c = 0; c < 4; c++) {
                float4 v = __ldg((const float4*)(Vb + (k0 + kq*4 + c)*DD + tx2*4));
                float pf0 = (&p0.x)[c], pf1 = (&p1.x)[c];
                float pf2 = (&p2.x)[c], pf3 = (&p3.x)[c];
                oacc[0].x += pf0*v.x; oacc[0].y += pf0*v.y; oacc[0].z += pf0*v.z; oacc[0].w += pf0*v.w;
                oacc[1].x += pf1*v.x; oacc[1].y += pf1*v.y; oacc[1].z += pf1*v.z; oacc[1].w += pf1*v.w;
                oacc[2].x += pf2*v.x; oacc[2].y += pf2*v.y; oacc[2].z += pf2*v.z; oacc[2].w += pf2*v.w;
                oacc[3].x += pf3*v.x; oacc[3].y += pf3*v.y; oacc[3].z += pf3*v.z; oacc[3].w += pf3*v.w;
            }
        }
    }

    float* dst = g_part[kc] + ((b << 10) + qt)*DD;
    #pragma unroll
    for (int i = 0; i < 4; i++)
        *(float4*)(dst + (ty2 + 8*i)*DD + tx2*4) = oacc[i];
    if (tx == 0) {
        g_rsum[kc][(b << 10) + qt + ty]      = rs0;
        g_rsum[kc][(b << 10) + qt + ty + 16] = rs1;
    }
}

// ---------------------------------------------------------------------------
// Reduce: sum active chunk partials + analytic masked term, normalize.
// ---------------------------------------------------------------------------
__global__ __launch_bounds__(256) void out_reduce_kernel(float* __restrict__ out,
                                                          const int* __restrict__ maskflag)
{
    const int causal = (maskflag[0] != 0);
    int idx4 = blockIdx.x * 256 + threadIdx.x;
    int base = idx4 * 4;
    int row  = base >> 7;              // b*SS + q
    int q    = row & (SS-1);
    int b    = row >> 10;

    int nc = causal ? (((q | 31) >> 7) + 1) : NCHUNK;

    float4 s = make_float4(0.f,0.f,0.f,0.f);
    float rsum = 0.f;
    for (int j = 0; j < nc; j++) {
        float4 p = *(const float4*)(&g_part[j][base]);
        s.x += p.x; s.y += p.y; s.z += p.z; s.w += p.w;
        rsum += g_rsum[j][row];
    }
    if (causal) {
        rsum += (float)(SS - 1 - q);           // masked entries: exp(0)=1 each
        int doff = base & 127;
        float4 vt = *(const float4*)(g_vpre + ((b << 10) + SS - 1)*DD + doff);
        float4 vp = *(const float4*)(g_vpre + row*DD + doff);
        s.x += vt.x - vp.x; s.y += vt.y - vp.y;
        s.z += vt.z - vp.z; s.w += vt.w - vp.w;
    }
    float rv = 1.f / rsum;
    s.x *= rv; s.y *= rv; s.z *= rv; s.w *= rv;
    *(float4*)(out + base) = s;
}

// ---------------------------------------------------------------------------
extern "C" void kernel_launch(void* const* d_in, const int* in_sizes, int n_in,
                              void* d_out, int out_size)
{
    const float* x  = (const float*)d_in[0];
    const float* Wq = (const float*)d_in[1];
    const float* bq = (const float*)d_in[2];
    const float* Wk = (const float*)d_in[3];
    const float* bk = (const float*)d_in[4];
    const float* Wv = (const float*)d_in[5];
    const float* bv = (const float*)d_in[6];
    const int*  msk = (const int*)d_in[7];
    float* out = (float*)d_out;

    qkv_kernel    <<<dim3(BB*SS/32, 3), 256>>>(x, Wq, bq, Wk, bk, Wv, bv);
    vseg_kernel   <<<dim3(BB, 16), 128>>>();
    vpre_kernel   <<<dim3(BB, 16), 128>>>();
    fused_kernel  <<<dim3(SS/32, BB, NCHUNK), 256>>>(msk);
    out_reduce_kernel<<<BB*SS*DD/1024, 256>>>(out, msk);
}

// round 5
// speedup vs baseline: 1.9689x; 1.3602x over previous
#include <cuda_runtime.h>

#define BB 2
#define SS 1024
#define DD 128
#define NCHUNK 8           // k chunks of 128

// Scratch (device globals; allocation-free per harness rules)
__device__ float g_Q[BB*SS*DD];
__device__ float g_K[BB*SS*DD];
__device__ float g_V[BB*SS*DD];
__device__ float g_sQ[BB*SS];                 // row sums of Q
__device__ float g_sK[BB*SS];                 // row sums of K
__device__ float g_part[NCHUNK][BB*SS*DD];    // split-K partial outputs (P-1 weighted)
__device__ float g_rsum[NCHUNK][BB*SS];       // split-K partial row sums of exp
__device__ float g_vseg[BB*16*DD];            // per-64-row segment sums of V

// ---------------------------------------------------------------------------
// K1: Q/K/V projection + row-sum epilogue for Q,K.  64-d chunks (2 iters).
// ---------------------------------------------------------------------------
__global__ __launch_bounds__(256) void qkv_kernel(
    const float* __restrict__ x,
    const float* __restrict__ Wq, const float* __restrict__ bq,
    const float* __restrict__ Wk, const float* __restrict__ bk,
    const float* __restrict__ Wv, const float* __restrict__ bv)
{
    __shared__ float xs[32*66];
    __shared__ float ws[128*66];
    const int t  = threadIdx.x;
    const int tx = t & 15;
    const int ty = t >> 4;
    const int mat = blockIdx.y;
    const int rowbase = blockIdx.x * 32;

    const float* W    = (mat == 0) ? Wq : (mat == 1) ? Wk : Wv;
    const float* bias = (mat == 0) ? bq : (mat == 1) ? bk : bv;

    float acc[2][8];
    #pragma unroll
    for (int i = 0; i < 2; i++)
        #pragma unroll
        for (int j = 0; j < 8; j++) acc[i][j] = 0.f;

    for (int dc = 0; dc < DD; dc += 64) {
        __syncthreads();
        #pragma unroll
        for (int i = 0; i < 32; i++) {          // W chunk [128][64]
            int lin = t + i*256;
            int e = lin >> 6, dd = lin & 63;
            ws[e*66 + dd] = W[e*DD + dc + dd];
        }
        #pragma unroll
        for (int i = 0; i < 8; i++) {           // x chunk [32][64]
            int lin = t + i*256;
            int r = lin >> 6, dd = lin & 63;
            xs[r*66 + dd] = x[(rowbase + r)*DD + dc + dd];
        }
        __syncthreads();
        #pragma unroll 8
        for (int d = 0; d < 64; d++) {
            float x0 = xs[ty*66 + d];
            float x1 = xs[(ty+16)*66 + d];
            #pragma unroll
            for (int j = 0; j < 8; j++) {
                float w = ws[(tx + 16*j)*66 + d];
                acc[0][j] += x0 * w;
                acc[1][j] += x1 * w;
            }
        }
    }

    float* out = (mat == 0) ? g_Q : (mat == 1) ? g_K : g_V;
    float rsum[2] = {0.f, 0.f};
    #pragma unroll
    for (int i = 0; i < 2; i++) {
        int r = rowbase + ty + 16*i;
        #pragma unroll
        for (int j = 0; j < 8; j++) {
            int e = tx + 16*j;
            float v = acc[i][j] + bias[e];
            if (mat < 2) v = 1.f / (1.f + __expf(-v));
            rsum[i] += v;
            out[r*DD + e] = v;
        }
    }
    if (mat < 2) {
        #pragma unroll
        for (int o = 1; o < 16; o <<= 1) {
            rsum[0] += __shfl_xor_sync(0xffffffffu, rsum[0], o);
            rsum[1] += __shfl_xor_sync(0xffffffffu, rsum[1], o);
        }
        if (tx == 0) {
            float* dst = (mat == 0) ? g_sQ : g_sK;
            dst[rowbase + ty]      = rsum[0];
            dst[rowbase + ty + 16] = rsum[1];
        }
    }
}

// ---------------------------------------------------------------------------
// V segment sums (Vtot assembled in the reduce from these 16 segments).
// ---------------------------------------------------------------------------
__global__ __launch_bounds__(128) void vseg_kernel()
{
    int b = blockIdx.x, s = blockIdx.y, d = threadIdx.x;
    const float* Vb = g_V + b*SS*DD;
    float a = 0.f;
    #pragma unroll 8
    for (int r = 0; r < 64; r++) a += Vb[(s*64 + r)*DD + d];
    g_vseg[(b*16 + s)*DD + d] = a;
}

// ---------------------------------------------------------------------------
// Fused flash-style kernel with triangular block mapping.
// One block = one ACTIVE (32-q tile, 128-k chunk) pair; no dead blocks in
// causal mode except the 112/batch that exit before any smem work.
// Stores (exp - 1) weighted PV partials; masked entries are exactly 0 under
// the P' = P-1 identity, leaving only a Vtot correction in the reduce.
// grid (256, B), block 256.
// ---------------------------------------------------------------------------
__global__ __launch_bounds__(256) void fused_kernel(const int* __restrict__ maskflag)
{
    const int causal = (maskflag[0] != 0);
    const int n = blockIdx.x;
    int qi, kc;
    if (causal) {
        if (n >= 144) return;
        // groups g of 4 q-tiles; base(g) = 2g(g+1), group size 4(g+1)
        int g = 0;
        while (g < 7 && 2*(g+1)*(g+2) <= n) g++;
        int r = n - 2*g*(g+1);
        int w = r / (g+1);
        qi = 4*g + w;
        kc = r - w*(g+1);
    } else {
        qi = n >> 3;
        kc = n & 7;
    }
    const int qt = qi * 32;

    __shared__ float qs[32*132];   // Q tile (16B-aligned rows: 132*4=528)
    __shared__ float ks[32*132];   // K subtile
    __shared__ float ss[32*36];    // (exp-1) score subtile

    const int t  = threadIdx.x;
    const int tx = t & 15;         // score: k = k0 + tx, +16
    const int ty = t >> 4;         // score: q = qt + ty, +16
    const int tx2 = t & 31;        // pv: d = tx2*4
    const int ty2 = t >> 5;        // pv: q = ty2 + 8i
    const int b  = blockIdx.y;

    const float* Qb = g_Q + b*SS*DD;
    const float* Kb = g_K + b*SS*DD;
    const float* Vb = g_V + b*SS*DD;

    // load Q tile [32][128]
    #pragma unroll
    for (int i = 0; i < 4; i++) {
        int lin = t + i*256;
        int r = lin >> 5, c = (lin & 31) * 4;
        *(float4*)(qs + r*132 + c) = *(const float4*)(Qb + (qt + r)*DD + c);
    }
    const float sQ0 = g_sQ[b*SS + qt + ty];
    const float sQ1 = g_sQ[b*SS + qt + ty + 16];

    float4 oacc[4];
    #pragma unroll
    for (int i = 0; i < 4; i++) oacc[i] = make_float4(0.f,0.f,0.f,0.f);
    float rs0 = 0.f, rs1 = 0.f;

    for (int s = 0; s < 4; s++) {
        const int k0 = kc*128 + s*32;
        if (causal && k0 > qt + 31) break;

        __syncthreads();
        #pragma unroll
        for (int i = 0; i < 4; i++) {          // load K subtile [32][128]
            int lin = t + i*256;
            int r = lin >> 5, c = (lin & 31) * 4;
            *(float4*)(ks + r*132 + c) = *(const float4*)(Kb + (k0 + r)*DD + c);
        }
        __syncthreads();

        // --- score: A = sum_d |q - k| (abs is a free FADD src modifier) ---
        float a00 = 0.f, a01 = 0.f, a10 = 0.f, a11 = 0.f;
        #pragma unroll 8
        for (int dq = 0; dq < 32; dq++) {
            float4 q0 = *(const float4*)(qs + ty*132 + dq*4);
            float4 q1 = *(const float4*)(qs + (ty+16)*132 + dq*4);
            float4 k0v = *(const float4*)(ks + tx*132 + dq*4);
            float4 k1v = *(const float4*)(ks + (tx+16)*132 + dq*4);
            a00 += fabsf(q0.x-k0v.x); a00 += fabsf(q0.y-k0v.y);
            a00 += fabsf(q0.z-k0v.z); a00 += fabsf(q0.w-k0v.w);
            a01 += fabsf(q0.x-k1v.x); a01 += fabsf(q0.y-k1v.y);
            a01 += fabsf(q0.z-k1v.z); a01 += fabsf(q0.w-k1v.w);
            a10 += fabsf(q1.x-k0v.x); a10 += fabsf(q1.y-k0v.y);
            a10 += fabsf(q1.z-k0v.z); a10 += fabsf(q1.w-k0v.w);
            a11 += fabsf(q1.x-k1v.x); a11 += fabsf(q1.y-k1v.y);
            a11 += fabsf(q1.z-k1v.z); a11 += fabsf(q1.w-k1v.w);
        }
        const float sK0 = g_sK[b*SS + k0 + tx];
        const float sK1 = g_sK[b*SS + k0 + tx + 16];

        // truth = 1 - (sQ - sK + A)/256 ; e = exp(10*truth)
        float e00 = __expf(10.f - (sQ0 - sK0 + a00)*(10.f/256.f));
        float e01 = __expf(10.f - (sQ0 - sK1 + a01)*(10.f/256.f));
        float e10 = __expf(10.f - (sQ1 - sK0 + a10)*(10.f/256.f));
        float e11 = __expf(10.f - (sQ1 - sK1 + a11)*(10.f/256.f));
        if (causal) {
            int q0g = qt + ty, q1g = qt + ty + 16;
            int k0g = k0 + tx, k1g = k0 + tx + 16;
            if (k0g > q0g) e00 = 0.f;       // excluded from rsum; ss becomes... see below
            if (k1g > q0g) e01 = 0.f;
            if (k0g > q1g) e10 = 0.f;
            if (k1g > q1g) e11 = 0.f;
        }
        // rsum counts only unmasked exp values
        float l0 = e00 + e01, l1 = e10 + e11;
        #pragma unroll
        for (int o = 1; o < 16; o <<= 1) {
            l0 += __shfl_xor_sync(0xffffffffu, l0, o);
            l1 += __shfl_xor_sync(0xffffffffu, l1, o);
        }
        if (tx == 0) { rs0 += l0; rs1 += l1; }

        // store (e - 1) for unmasked, 0 for masked (P'=P-1 identity)
        ss[ty*36 + tx]           = (e00 == 0.f) ? 0.f : e00 - 1.f;
        ss[ty*36 + tx + 16]      = (e01 == 0.f) ? 0.f : e01 - 1.f;
        ss[(ty+16)*36 + tx]      = (e10 == 0.f) ? 0.f : e10 - 1.f;
        ss[(ty+16)*36 + tx + 16] = (e11 == 0.f) ? 0.f : e11 - 1.f;
        __syncthreads();

        // --- PV: oacc[q][d] += sum_k ss[q][k] * V[k][d]; V from L1/L2 ---
        #pragma unroll 2
        for (int kq = 0; kq < 8; kq++) {
            float4 p0 = *(const float4*)(ss + (ty2    )*36 + kq*4);
            float4 p1 = *(const float4*)(ss + (ty2+ 8)*36 + kq*4);
            float4 p2 = *(const float4*)(ss + (ty2+16)*36 + kq*4);
            float4 p3 = *(const float4*)(ss + (ty2+24)*36 + kq*4);
            #pragma unroll
            for (int c = 0; c < 4; c++) {
                float4 v = __ldg((const float4*)(Vb + (k0 + kq*4 + c)*DD + tx2*4));
                float pf0 = (&p0.x)[c], pf1 = (&p1.x)[c];
                float pf2 = (&p2.x)[c], pf3 = (&p3.x)[c];
                oacc[0].x += pf0*v.x; oacc[0].y += pf0*v.y; oacc[0].z += pf0*v.z; oacc[0].w += pf0*v.w;
                oacc[1].x += pf1*v.x; oacc[1].y += pf1*v.y; oacc[1].z += pf1*v.z; oacc[1].w += pf1*v.w;
                oacc[2].x += pf2*v.x; oacc[2].y += pf2*v.y; oacc[2].z += pf2*v.z; oacc[2].w += pf2*v.w;
                oacc[3].x += pf3*v.x; oacc[3].y += pf3*v.y; oacc[3].z += pf3*v.z; oacc[3].w += pf3*v.w;
            }
        }
    }

    float* dst = g_part[kc] + ((b << 10) + qt)*DD;
    #pragma unroll
    for (int i = 0; i < 4; i++)
        *(float4*)(dst + (ty2 + 8*i)*DD + tx2*4) = oacc[i];
    if (tx == 0) {
        g_rsum[kc][(b << 10) + qt + ty]      = rs0;
        g_rsum[kc][(b << 10) + qt + ty + 16] = rs1;
    }
}

// ---------------------------------------------------------------------------
// Reduce: sum active chunk partials + Vtot (from vseg) , normalize.
// out = (sum_chunks part + Vtot) / (sum_chunks rsum + masked_count)
// ---------------------------------------------------------------------------
__global__ __launch_bounds__(256) void out_reduce_kernel(float* __restrict__ out,
                                                          const int* __restrict__ maskflag)
{
    const int causal = (maskflag[0] != 0);
    int idx4 = blockIdx.x * 256 + threadIdx.x;
    int base = idx4 * 4;
    int row  = base >> 7;              // b*SS + q
    int q    = row & (SS-1);
    int b    = row >> 10;
    int doff = base & 127;

    int nc = causal ? ((q >> 7) + 1) : NCHUNK;

    float4 s = make_float4(0.f,0.f,0.f,0.f);
    float rsum = 0.f;
    for (int j = 0; j < nc; j++) {
        float4 p = *(const float4*)(&g_part[j][base]);
        s.x += p.x; s.y += p.y; s.z += p.z; s.w += p.w;
        rsum += g_rsum[j][row];
    }
    // + Vtot  (P' = P-1 identity: every k contributes 1*V[k])
    #pragma unroll
    for (int seg = 0; seg < 16; seg++) {
        float4 vs4 = *(const float4*)(g_vseg + ((b*16 + seg) << 7) + doff);
        s.x += vs4.x; s.y += vs4.y; s.z += vs4.z; s.w += vs4.w;
    }
    if (causal) rsum += (float)(SS - 1 - q);   // masked entries: exp(0)=1 each

    float rv = 1.f / rsum;
    s.x *= rv; s.y *= rv; s.z *= rv; s.w *= rv;
    *(float4*)(out + base) = s;
}

// ---------------------------------------------------------------------------
extern "C" void kernel_launch(void* const* d_in, const int* in_sizes, int n_in,
                              void* d_out, int out_size)
{
    const float* x  = (const float*)d_in[0];
    const float* Wq = (const float*)d_in[1];
    const float* bq = (const float*)d_in[2];
    const float* Wk = (const float*)d_in[3];
    const float* bk = (const float*)d_in[4];
    const float* Wv = (const float*)d_in[5];
    const float* bv = (const float*)d_in[6];
    const int*  msk = (const int*)d_in[7];
    float* out = (float*)d_out;

    qkv_kernel    <<<dim3(BB*SS/32, 3), 256>>>(x, Wq, bq, Wk, bk, Wv, bv);
    vseg_kernel   <<<dim3(BB, 16), 128>>>();
    fused_kernel  <<<dim3(256, BB), 256>>>(msk);
    out_reduce_kernel<<<BB*SS*DD/1024, 256>>>(out, msk);
}